// round 3
// baseline (speedup 1.0000x reference)
#include <cuda_runtime.h>

// PerturbedTopK:
//   x: (64, 196) f32, noise: (64, 500, 196) f32
//   perturbed = x + SIGMA*noise; per (b,n) row take top-49 indices of 196,
//   sort indices ascending, out[b,k,d] = mean_n [sorted_idx[b,n,k] == d].
//
// One warp per row, 7 values/lane in registers.
// HOT: threshold search for count(val > piv) == 49 exactly, using
//   regula-falsi alternated with bisection (expected ~4-5 evals). Counting
//   via single-instruction FSET (set.gt.u32.f32 -> 0xFFFFFFFF) + REDUX.
//   Exactly-49 strictly-above => no ties; rank by ascending index via
//   ballot prefix sums; atomicAdd(1/500).
// COLD (cap hit or tie at the boundary): exact MSB radix select with
//   index-order tie-break (proven in round 2).

#define BATCH 64
#define NSAMP 500
#define DIM   196
#define TOPK  49
#define SIGMA 0.05f

#define NROWS (BATCH * NSAMP)
#define OUTN  (BATCH * TOPK * DIM)
#define FULLM 0xffffffffu

__global__ void zero_out_kernel(float* __restrict__ out, int n) {
    int i = blockIdx.x * blockDim.x + threadIdx.x;
    if (i < n) out[i] = 0.0f;
}

__device__ __forceinline__ unsigned f2key(float v) {
    unsigned u = __float_as_uint(v);
    return u ^ ((unsigned)((int)u >> 31) | 0x80000000u);
}

// 0xFFFFFFFF if a > b else 0 (single SASS FSET).
__device__ __forceinline__ unsigned fgt(float a, float b) {
    unsigned r;
    asm("set.gt.u32.f32 %0, %1, %2;" : "=r"(r) : "f"(a), "f"(b));
    return r;
}

__global__ __launch_bounds__(256, 6)
void ptopk_kernel(const float* __restrict__ x,
                  const float* __restrict__ noise,
                  float* __restrict__ out) {
    const int warp = threadIdx.x >> 5;
    const int lane = threadIdx.x & 31;
    const int row  = blockIdx.x * 8 + warp;
    if (row >= NROWS) return;

    const int b = row / NSAMP;
    const float* __restrict__ xr = x + b * DIM;
    const float* __restrict__ nr = noise + (size_t)row * DIM;
    const unsigned lt = (1u << lane) - 1u;
    const float invn = 1.0f / (float)NSAMP;
    float* __restrict__ outb = out + b * (TOPK * DIM);

    float val[7];
    #pragma unroll
    for (int j = 0; j < 7; j++) {
        const int d = j * 32 + lane;
        val[j] = (d < DIM) ? fmaf(nr[d], SIGMA, xr[d]) : -3.402823466e38f;
    }

    // ---- HOT: falsi/bisection hybrid for count(val > piv) == TOPK ----
    float lo = -6.0f, hi = 6.0f;      // virtual endpoints (data is ~N(0,1)+-0.25)
    int clo = DIM, chi = 0;           // counts at lo / hi
    float piv = 0.70f;                // ~expected 49/196 quantile
    float T = 0.0f;
    int found = 0;

    #pragma unroll 1
    for (int it = 0; it < 20; ++it) {
        unsigned a = 0;
        #pragma unroll
        for (int j = 0; j < 7; j++) a += fgt(val[j], piv);   // adds -1 per hit
        const int c = -(int)__reduce_add_sync(FULLM, (int)a);
        if (c == TOPK) { T = piv; found = 1; break; }
        const bool g = (c > TOPK);
        lo  = g ? piv : lo;   clo = g ? c : clo;
        hi  = g ? hi  : piv;  chi = g ? chi : c;
        const float w = hi - lo;
        float p;
        if (it & 1) {
            p = fmaf(w, 0.5f, lo);                           // bisection step
        } else {                                             // regula falsi step
            const float f = (float)(clo - TOPK) * __fdividef(1.0f, (float)(clo - chi));
            p = fmaf(w, f, lo);
            p = fminf(fmaxf(p, fmaf(w, 0.03125f, lo)), fmaf(w, -0.03125f, hi));
        }
        piv = p;
    }

    if (found) {
        // Exactly TOPK strictly above T: tie-free. Rank by ascending index.
        int base = 0;
        #pragma unroll
        for (int j = 0; j < 7; j++) {
            const int d = j * 32 + lane;
            const bool s = val[j] > T;
            const unsigned mb = __ballot_sync(FULLM, s);
            if (s) {
                const int rank = base + __popc(mb & lt);
                atomicAdd(outb + rank * DIM + d, invn);
            }
            base += __popc(mb);
        }
        return;
    }

    // ---- COLD: exact MSB radix select with index-order tie-break ----
    unsigned actm = (6 * 32 + lane < DIM) ? 0x7Fu : 0x3Fu;
    int k = TOPK;
    int matching = DIM;
    unsigned P = 0u;
    int s = 0;
    #pragma unroll 1
    for (int bit = 31; bit >= 0; --bit) {
        const unsigned m = 1u << bit;
        int c = 0;
        #pragma unroll
        for (int j = 0; j < 7; j++)
            c += (((actm >> j) & 1u) && (f2key(val[j]) & m)) ? 1 : 0;
        c = __reduce_add_sync(FULLM, c);
        if (c >= k) {
            P |= m;
            matching = c;
            #pragma unroll
            for (int j = 0; j < 7; j++)
                if (!(f2key(val[j]) & m)) actm &= ~(1u << j);
        } else {
            k -= c;
            matching -= c;
            #pragma unroll
            for (int j = 0; j < 7; j++)
                if (f2key(val[j]) & m) actm &= ~(1u << j);
        }
        s = bit;
        if (matching == k) break;
    }

    const unsigned Ph = P >> s;
    int gtb = 0, eqb = 0;
    #pragma unroll
    for (int j = 0; j < 7; j++) {
        const int d = j * 32 + lane;
        const bool gt = (d < DIM) && ((f2key(val[j]) >> s) > Ph);
        const bool eq = ((actm >> j) & 1u) != 0u;
        const unsigned mg = __ballot_sync(FULLM, gt);
        const unsigned me = __ballot_sync(FULLM, eq);
        const int gtp = gtb + __popc(mg & lt);
        const int eqp = eqb + __popc(me & lt);
        if (gt || (eq && eqp < k)) {
            const int rank = gtp + min(eqp, k);
            atomicAdd(outb + rank * DIM + d, invn);
        }
        gtb += __popc(mg);
        eqb += __popc(me);
    }
}

extern "C" void kernel_launch(void* const* d_in, const int* in_sizes, int n_in,
                              void* d_out, int out_size) {
    const float* x     = (const float*)d_in[0];
    const float* noise = (const float*)d_in[1];
    if (n_in >= 2 && in_sizes[0] > in_sizes[1]) {
        x     = (const float*)d_in[1];
        noise = (const float*)d_in[0];
    }
    float* out = (float*)d_out;

    zero_out_kernel<<<(OUTN + 255) / 256, 256>>>(out, OUTN);
    ptopk_kernel<<<(NROWS + 7) / 8, 256>>>(x, noise, out);
}

// round 4
// speedup vs baseline: 1.2000x; 1.2000x over previous
#include <cuda_runtime.h>

// PerturbedTopK:
//   x: (64, 196) f32, noise: (64, 500, 196) f32
//   perturbed = x + SIGMA*noise; per (b,n) row take top-49 indices of 196,
//   sort indices ascending, out[b,k,d] = mean_n [sorted_idx[b,n,k] == d].
//
// One warp per row, 7 values/lane in registers. grid=(125,64): y=batch,
// 4 warps/block * 125 blocks = exactly 500 rows per batch (no div, no guard).
//
// HOT: find pivot with count(val > piv) == 49 exactly.
//   Iters 0-2: Newton steps using the known Gaussian density slope
//              (dc/dt ~ 196*phi(0.674) ~ 60 -> step = (c-49)*0.017),
//              clamped into the maintained bracket. Iters 3+: pure bisection.
//   Counting: single-SASS-instruction FSET (set.gt.u32.f32) + REDUX.
//   Exactly-49 strictly above => tie-free; rank by ascending index via
//   ballot prefix sums; atomicAdd(1/500).
// COLD (cap hit / tie straddling boundary): exact MSB radix select with
//   index-order tie-break (proven round 2). Preserves exactness always.

#define BATCH 64
#define NSAMP 500
#define DIM   196
#define TOPK  49
#define SIGMA 0.05f

#define OUTN  (BATCH * TOPK * DIM)
#define FULLM 0xffffffffu

__device__ __forceinline__ unsigned f2key(float v) {
    unsigned u = __float_as_uint(v);
    return u ^ ((unsigned)((int)u >> 31) | 0x80000000u);
}

// 0xFFFFFFFF if a > b else 0 (single SASS FSET).
__device__ __forceinline__ unsigned fgt(float a, float b) {
    unsigned r;
    asm("set.gt.u32.f32 %0, %1, %2;" : "=r"(r) : "f"(a), "f"(b));
    return r;
}

__global__ __launch_bounds__(128)
void ptopk_kernel(const float* __restrict__ x,
                  const float* __restrict__ noise,
                  float* __restrict__ out) {
    const int warp = threadIdx.x >> 5;
    const int lane = threadIdx.x & 31;
    const int b    = blockIdx.y;
    const int rib  = blockIdx.x * 4 + warp;        // row in batch, [0, 500)

    const float* __restrict__ xr = x + b * DIM;
    const float* __restrict__ nr = noise + ((size_t)b * NSAMP + rib) * DIM;
    const unsigned lt = (1u << lane) - 1u;
    const float invn = 1.0f / (float)NSAMP;
    float* __restrict__ outb = out + b * (TOPK * DIM);

    float val[7];
    #pragma unroll
    for (int j = 0; j < 7; j++) {
        const int d = j * 32 + lane;
        val[j] = (d < DIM) ? fmaf(nr[d], SIGMA, xr[d]) : -3.402823466e38f;
    }

    // ---- HOT: Newton-seeded bisection for count(val > piv) == TOPK ----
    float lo = 0.0f, hi = 1.5f;
    float piv = 0.68f;                 // ~ 49/196 Gaussian quantile
    float T = 0.0f;
    int found = 0;

    #pragma unroll 1
    for (int it = 0; it < 20; ++it) {
        unsigned a = 0;
        #pragma unroll
        for (int j = 0; j < 7; j++) a += fgt(val[j], piv);   // -1 per hit
        const int c = -(int)a;
        const int ct = __reduce_add_sync(FULLM, c);
        if (ct == TOPK) { T = piv; found = 1; break; }
        const bool g = (ct > TOPK);
        lo = g ? piv : lo;
        hi = g ? hi  : piv;
        if (it < 3) {
            // Newton step with fixed density slope; clamp inside bracket.
            const float w = hi - lo;
            float p = fmaf((float)(ct - TOPK), 0.017f, piv);
            p = fmaxf(p, fmaf(w, 0.0625f, lo));
            p = fminf(p, fmaf(w, -0.0625f, hi));
            piv = p;
        } else {
            piv = 0.5f * (lo + hi);
        }
    }

    if (found) {
        // Exactly TOPK strictly above T: tie-free. Rank by ascending index.
        int base = 0;
        #pragma unroll
        for (int j = 0; j < 7; j++) {
            const int d = j * 32 + lane;
            const bool s = val[j] > T;
            const unsigned mb = __ballot_sync(FULLM, s);
            if (s) {
                const int rank = base + __popc(mb & lt);
                atomicAdd(outb + rank * DIM + d, invn);
            }
            base += __popc(mb);
        }
        return;
    }

    // ---- COLD: exact MSB radix select with index-order tie-break ----
    unsigned actm = (6 * 32 + lane < DIM) ? 0x7Fu : 0x3Fu;
    int k = TOPK;
    int matching = DIM;
    unsigned P = 0u;
    int s = 0;
    #pragma unroll 1
    for (int bit = 31; bit >= 0; --bit) {
        const unsigned m = 1u << bit;
        int c = 0;
        #pragma unroll
        for (int j = 0; j < 7; j++)
            c += (((actm >> j) & 1u) && (f2key(val[j]) & m)) ? 1 : 0;
        c = __reduce_add_sync(FULLM, c);
        if (c >= k) {
            P |= m;
            matching = c;
            #pragma unroll
            for (int j = 0; j < 7; j++)
                if (!(f2key(val[j]) & m)) actm &= ~(1u << j);
        } else {
            k -= c;
            matching -= c;
            #pragma unroll
            for (int j = 0; j < 7; j++)
                if (f2key(val[j]) & m) actm &= ~(1u << j);
        }
        s = bit;
        if (matching == k) break;
    }

    const unsigned Ph = P >> s;
    int gtb = 0, eqb = 0;
    #pragma unroll
    for (int j = 0; j < 7; j++) {
        const int d = j * 32 + lane;
        const bool gt = (d < DIM) && ((f2key(val[j]) >> s) > Ph);
        const bool eq = ((actm >> j) & 1u) != 0u;
        const unsigned mg = __ballot_sync(FULLM, gt);
        const unsigned me = __ballot_sync(FULLM, eq);
        const int gtp = gtb + __popc(mg & lt);
        const int eqp = eqb + __popc(me & lt);
        if (gt || (eq && eqp < k)) {
            const int rank = gtp + min(eqp, k);
            atomicAdd(outb + rank * DIM + d, invn);
        }
        gtb += __popc(mg);
        eqb += __popc(me);
    }
}

extern "C" void kernel_launch(void* const* d_in, const int* in_sizes, int n_in,
                              void* d_out, int out_size) {
    const float* x     = (const float*)d_in[0];
    const float* noise = (const float*)d_in[1];
    if (n_in >= 2 && in_sizes[0] > in_sizes[1]) {
        x     = (const float*)d_in[1];
        noise = (const float*)d_in[0];
    }
    float* out = (float*)d_out;

    cudaMemsetAsync(out, 0, (size_t)OUTN * sizeof(float));
    dim3 grid(125, BATCH, 1);
    ptopk_kernel<<<grid, 128>>>(x, noise, out);
}